// round 6
// baseline (speedup 1.0000x reference)
#include <cuda_runtime.h>
#include <cuda_bf16.h>
#include <cstdint>

// ============================================================================
// NegativeContrastiveLoss: x[8192,256] fp32 ->
//   xn = x / max(||x||_2, 1e-12)  (rows)
//   S  = xn @ xn^T / 0.1 ; E = exp(S) with diag zeroed
//   loss = mean_i log( sum_j E_ij / (N-1) + 1e-8 )
//
// Toolchain note: bench compiles via compute_103 (family) PTX target, which
// rejects tcgen05.*. So we use the classic mma.sync m16n8k16 bf16 path
// (sm_80+ PTX, legal here) with ldmatrix from swizzled SMEM.
//
// Pipeline:
//   (1) k_normalize: row L2-normalize -> bf16 scratch g_xn; zero g_rowsum
//   (2) k_gemm: 128x128 tile GEMM (K=256, 2 chunks) fused with
//       exp(S/tau) + diagonal zeroing + per-row sum (atomicAdd)
//   (3) k_reduce: loss = mean log(rowsum/(N-1) + eps)
// ============================================================================

#define NROWS 8192
#define DIM   256
#define TAU_INV_LOG2E 14.4269504088896340736f   // (1/0.1) * log2(e)
#define EPS   1e-8f

__device__ __align__(256) __nv_bfloat16 g_xn[NROWS * DIM];   // 4 MB, L2-resident
__device__ float g_rowsum[NROWS];

static __device__ __forceinline__ unsigned smem_u32(const void* p) {
    unsigned a;
    asm("{ .reg .u64 t; cvta.to.shared.u64 t, %1; cvt.u32.u64 %0, t; }" : "=r"(a) : "l"(p));
    return a;
}

static __device__ __forceinline__ void ldmatrix_x4(unsigned& r0, unsigned& r1,
                                                   unsigned& r2, unsigned& r3,
                                                   unsigned addr) {
    asm volatile("ldmatrix.sync.aligned.m8n8.x4.shared.b16 {%0,%1,%2,%3}, [%4];"
                 : "=r"(r0), "=r"(r1), "=r"(r2), "=r"(r3) : "r"(addr));
}

static __device__ __forceinline__ void mma_16816(float* c, const unsigned* a,
                                                 const unsigned* b) {
    asm volatile(
        "mma.sync.aligned.m16n8k16.row.col.f32.bf16.bf16.f32 "
        "{%0,%1,%2,%3}, {%4,%5,%6,%7}, {%8,%9}, {%0,%1,%2,%3};"
        : "+f"(c[0]), "+f"(c[1]), "+f"(c[2]), "+f"(c[3])
        : "r"(a[0]), "r"(a[1]), "r"(a[2]), "r"(a[3]), "r"(b[0]), "r"(b[1]));
}

// ---------------------------------------------------------------------------
// Kernel 1: row L2-normalize -> bf16, zero rowsum. 1 warp per row.
// ---------------------------------------------------------------------------
__global__ __launch_bounds__(256) void k_normalize(const float* __restrict__ x) {
    int tid = threadIdx.x;
    int gt = blockIdx.x * 256 + tid;
    if (gt < NROWS) g_rowsum[gt] = 0.0f;

    int row  = blockIdx.x * 8 + (tid >> 5);
    int lane = tid & 31;
    const float4* xr = reinterpret_cast<const float4*>(x) + (size_t)row * (DIM / 4);
    float4 a = xr[lane * 2 + 0];
    float4 b = xr[lane * 2 + 1];
    float s = a.x * a.x + a.y * a.y + a.z * a.z + a.w * a.w +
              b.x * b.x + b.y * b.y + b.z * b.z + b.w * b.w;
#pragma unroll
    for (int o = 16; o; o >>= 1) s += __shfl_xor_sync(0xFFFFFFFFu, s, o);
    float scale = 1.0f / fmaxf(sqrtf(s), 1e-12f);

    __nv_bfloat162 p0 = __floats2bfloat162_rn(a.x * scale, a.y * scale);
    __nv_bfloat162 p1 = __floats2bfloat162_rn(a.z * scale, a.w * scale);
    __nv_bfloat162 p2 = __floats2bfloat162_rn(b.x * scale, b.y * scale);
    __nv_bfloat162 p3 = __floats2bfloat162_rn(b.z * scale, b.w * scale);
    uint4 o;
    o.x = *reinterpret_cast<unsigned*>(&p0);
    o.y = *reinterpret_cast<unsigned*>(&p1);
    o.z = *reinterpret_cast<unsigned*>(&p2);
    o.w = *reinterpret_cast<unsigned*>(&p3);
    reinterpret_cast<uint4*>(g_xn)[row * (DIM / 8) + lane] = o;
}

// ---------------------------------------------------------------------------
// Kernel 2: fused GEMM + exp + rowsum.
//
// CTA tile 128(M) x 128(N); K=256 in two 128-chunks. 8 warps as 4(M) x 2(N):
// warp tile 32x64. SMEM per chunk: A 128x128 bf16 (32 KB) + B 128x128 (32 KB),
// both row-major pitch 256B with 16B-granular XOR swizzle (^ (row&7)<<4) for
// conflict-free ldmatrix. A frags via ldmatrix.x4 (one m16k16 frag each);
// B frags via ldmatrix.x4 (two k16n8 frags each, no .trans needed since
// B tile holds xn[n][k] row-major == col-major k x n).
// Epilogue: exp2(acc * 10*log2e), zero exact diagonal, quad-shfl row-reduce,
// atomicAdd into g_rowsum.
// ---------------------------------------------------------------------------
#define SMEM_B_OFF 32768
#define SMEM_TOT   65536

__global__ __launch_bounds__(256) void k_gemm() {
    extern __shared__ char smem[];
    unsigned sb = smem_u32(smem);
    int tid  = threadIdx.x;
    int wid  = tid >> 5, lane = tid & 31;
    int bj = blockIdx.x;                 // N tile (cols bj*128..)
    int bi = blockIdx.y;                 // M tile (rows bi*128..)
    int warp_m = (wid & 3) * 32;
    int warp_n = (wid >> 2) * 64;

    float acc[2][8][4];
#pragma unroll
    for (int mf = 0; mf < 2; mf++)
#pragma unroll
        for (int nf = 0; nf < 8; nf++)
#pragma unroll
            for (int j = 0; j < 4; j++) acc[mf][nf][j] = 0.0f;

    const uint4* gx = reinterpret_cast<const uint4*>(g_xn);

    for (int kc = 0; kc < 2; kc++) {
        if (kc) __syncthreads();         // protect smem reuse
        // ---- load A,B chunks: 128 rows x 128 bf16 each (16 uint4 per row) ----
#pragma unroll
        for (int it = 0; it < 8; it++) {
            int i = tid + it * 256;
            int r = i >> 4, c = i & 15;
            uint4 v = gx[(size_t)(bi * 128 + r) * 32 + kc * 16 + c];
            *reinterpret_cast<uint4*>(smem + r * 256 + ((c << 4) ^ ((r & 7) << 4))) = v;
        }
#pragma unroll
        for (int it = 0; it < 8; it++) {
            int i = tid + it * 256;
            int r = i >> 4, c = i & 15;
            uint4 v = gx[(size_t)(bj * 128 + r) * 32 + kc * 16 + c];
            *reinterpret_cast<uint4*>(smem + SMEM_B_OFF + r * 256 +
                                      ((c << 4) ^ ((r & 7) << 4))) = v;
        }
        __syncthreads();

        // ---- 8 k16 steps ----
#pragma unroll
        for (int ks = 0; ks < 8; ks++) {
            unsigned a[2][4];
#pragma unroll
            for (int mf = 0; mf < 2; mf++) {
                int r   = warp_m + mf * 16 + (lane & 15);
                int seg = lane >> 4;                       // k half (0/8)
                unsigned addr = sb + r * 256 +
                                (((ks * 2 + seg) << 4) ^ ((r & 7) << 4));
                ldmatrix_x4(a[mf][0], a[mf][1], a[mf][2], a[mf][3], addr);
            }
            unsigned b[8][2];
#pragma unroll
            for (int p = 0; p < 4; p++) {                  // pairs of n8 frags
                int g = lane >> 3, lr = lane & 7;
                int r   = warp_n + p * 16 + (g >> 1) * 8 + lr;
                int seg = g & 1;                           // k half
                unsigned addr = sb + SMEM_B_OFF + r * 256 +
                                (((ks * 2 + seg) << 4) ^ ((r & 7) << 4));
                unsigned r0, r1, r2, r3;
                ldmatrix_x4(r0, r1, r2, r3, addr);
                b[p * 2 + 0][0] = r0; b[p * 2 + 0][1] = r1;
                b[p * 2 + 1][0] = r2; b[p * 2 + 1][1] = r3;
            }
#pragma unroll
            for (int mf = 0; mf < 2; mf++)
#pragma unroll
                for (int nf = 0; nf < 8; nf++)
                    mma_16816(acc[mf][nf], a[mf], b[nf]);
        }
    }

    // ---- epilogue: exp, zero diagonal, per-row partial sums ----
    float rs[4] = {0.0f, 0.0f, 0.0f, 0.0f};   // rows: wm+l/4 +{0,8,16,24}
#pragma unroll
    for (int mf = 0; mf < 2; mf++) {
        int grow0 = bi * 128 + warp_m + mf * 16 + (lane >> 2);
#pragma unroll
        for (int nf = 0; nf < 8; nf++) {
            int gcol0 = bj * 128 + warp_n + nf * 8 + (lane & 3) * 2;
            float e0, e1, e2, e3;
            asm("ex2.approx.f32 %0, %1;" : "=f"(e0) : "f"(acc[mf][nf][0] * TAU_INV_LOG2E));
            asm("ex2.approx.f32 %0, %1;" : "=f"(e1) : "f"(acc[mf][nf][1] * TAU_INV_LOG2E));
            asm("ex2.approx.f32 %0, %1;" : "=f"(e2) : "f"(acc[mf][nf][2] * TAU_INV_LOG2E));
            asm("ex2.approx.f32 %0, %1;" : "=f"(e3) : "f"(acc[mf][nf][3] * TAU_INV_LOG2E));
            rs[mf * 2 + 0] += (gcol0     == grow0    ) ? 0.0f : e0;
            rs[mf * 2 + 0] += (gcol0 + 1 == grow0    ) ? 0.0f : e1;
            rs[mf * 2 + 1] += (gcol0     == grow0 + 8) ? 0.0f : e2;
            rs[mf * 2 + 1] += (gcol0 + 1 == grow0 + 8) ? 0.0f : e3;
        }
    }
#pragma unroll
    for (int o = 1; o <= 2; o <<= 1) {
#pragma unroll
        for (int j = 0; j < 4; j++)
            rs[j] += __shfl_xor_sync(0xFFFFFFFFu, rs[j], o);
    }
    if ((lane & 3) == 0) {
        int r0 = bi * 128 + warp_m + (lane >> 2);
        atomicAdd(&g_rowsum[r0],      rs[0]);
        atomicAdd(&g_rowsum[r0 + 8],  rs[1]);
        atomicAdd(&g_rowsum[r0 + 16], rs[2]);
        atomicAdd(&g_rowsum[r0 + 24], rs[3]);
    }
}

// ---------------------------------------------------------------------------
// Kernel 3: loss = mean_i log(rowsum_i / (N-1) + eps)
// ---------------------------------------------------------------------------
__global__ __launch_bounds__(256) void k_reduce(float* __restrict__ out) {
    __shared__ float sh[8];
    int tid = threadIdx.x;
    float s = 0.0f;
    for (int i = tid; i < NROWS; i += 256)
        s += logf(g_rowsum[i] * (1.0f / (float)(NROWS - 1)) + EPS);
#pragma unroll
    for (int o = 16; o; o >>= 1) s += __shfl_xor_sync(0xFFFFFFFFu, s, o);
    if ((tid & 31) == 0) sh[tid >> 5] = s;
    __syncthreads();
    if (tid == 0) {
        float t = 0.0f;
#pragma unroll
        for (int i = 0; i < 8; i++) t += sh[i];
        out[0] = t * (1.0f / (float)NROWS);
    }
}

// ---------------------------------------------------------------------------
extern "C" void kernel_launch(void* const* d_in, const int* in_sizes, int n_in,
                              void* d_out, int out_size) {
    (void)in_sizes; (void)n_in; (void)out_size;
    const float* x = (const float*)d_in[0];

    cudaFuncSetAttribute(k_gemm, cudaFuncAttributeMaxDynamicSharedMemorySize, SMEM_TOT);

    k_normalize<<<NROWS / 8, 256>>>(x);
    k_gemm<<<dim3(64, 64), 256, SMEM_TOT>>>();
    k_reduce<<<1, 256>>>((float*)d_out);
}

// round 7
// speedup vs baseline: 1.0739x; 1.0739x over previous
#include <cuda_runtime.h>
#include <cuda_bf16.h>
#include <cstdint>

// ============================================================================
// NegativeContrastiveLoss: x[8192,256] fp32 ->
//   xn = x / max(||x||_2, 1e-12)  (rows)
//   S  = xn @ xn^T / 0.1 ; E = exp(S) with diag zeroed
//   loss = mean_i log( sum_j E_ij / (N-1) + 1e-8 )
//
// R6: exploit symmetry E_ij = E_ji. Compute only upper-triangular 128x128
// tiles (2080 instead of 4096). Off-diagonal tiles add their row sums to
// block bi and their column sums (via shfl + smem reduce) to block bj.
//
// Classic mma.sync m16n8k16 bf16 path (compute_103 family target rejects
// tcgen05.*, so tensor work goes through HMMA + ldmatrix).
// ============================================================================

#define NROWS 8192
#define DIM   256
#define TAU_INV_LOG2E 14.4269504088896340736f   // (1/0.1) * log2(e)
#define EPS   1e-8f

__device__ __align__(256) __nv_bfloat16 g_xn[NROWS * DIM];   // 4 MB, L2-resident
__device__ float g_rowsum[NROWS];

static __device__ __forceinline__ unsigned smem_u32(const void* p) {
    unsigned a;
    asm("{ .reg .u64 t; cvta.to.shared.u64 t, %1; cvt.u32.u64 %0, t; }" : "=r"(a) : "l"(p));
    return a;
}

static __device__ __forceinline__ void ldmatrix_x4(unsigned& r0, unsigned& r1,
                                                   unsigned& r2, unsigned& r3,
                                                   unsigned addr) {
    asm volatile("ldmatrix.sync.aligned.m8n8.x4.shared.b16 {%0,%1,%2,%3}, [%4];"
                 : "=r"(r0), "=r"(r1), "=r"(r2), "=r"(r3) : "r"(addr));
}

static __device__ __forceinline__ void mma_16816(float* c, const unsigned* a,
                                                 const unsigned* b) {
    asm volatile(
        "mma.sync.aligned.m16n8k16.row.col.f32.bf16.bf16.f32 "
        "{%0,%1,%2,%3}, {%4,%5,%6,%7}, {%8,%9}, {%0,%1,%2,%3};"
        : "+f"(c[0]), "+f"(c[1]), "+f"(c[2]), "+f"(c[3])
        : "r"(a[0]), "r"(a[1]), "r"(a[2]), "r"(a[3]), "r"(b[0]), "r"(b[1]));
}

static __device__ __forceinline__ float ex2f(float v) {
    float e;
    asm("ex2.approx.f32 %0, %1;" : "=f"(e) : "f"(v));
    return e;
}

// ---------------------------------------------------------------------------
// Kernel 1: row L2-normalize -> bf16, zero rowsum. 1 warp per row.
// ---------------------------------------------------------------------------
__global__ __launch_bounds__(256) void k_normalize(const float* __restrict__ x) {
    int tid = threadIdx.x;
    int gt = blockIdx.x * 256 + tid;
    if (gt < NROWS) g_rowsum[gt] = 0.0f;

    int row  = blockIdx.x * 8 + (tid >> 5);
    int lane = tid & 31;
    const float4* xr = reinterpret_cast<const float4*>(x) + (size_t)row * (DIM / 4);
    float4 a = xr[lane * 2 + 0];
    float4 b = xr[lane * 2 + 1];
    float s = a.x * a.x + a.y * a.y + a.z * a.z + a.w * a.w +
              b.x * b.x + b.y * b.y + b.z * b.z + b.w * b.w;
#pragma unroll
    for (int o = 16; o; o >>= 1) s += __shfl_xor_sync(0xFFFFFFFFu, s, o);
    float scale = 1.0f / fmaxf(sqrtf(s), 1e-12f);

    __nv_bfloat162 p0 = __floats2bfloat162_rn(a.x * scale, a.y * scale);
    __nv_bfloat162 p1 = __floats2bfloat162_rn(a.z * scale, a.w * scale);
    __nv_bfloat162 p2 = __floats2bfloat162_rn(b.x * scale, b.y * scale);
    __nv_bfloat162 p3 = __floats2bfloat162_rn(b.z * scale, b.w * scale);
    uint4 o;
    o.x = *reinterpret_cast<unsigned*>(&p0);
    o.y = *reinterpret_cast<unsigned*>(&p1);
    o.z = *reinterpret_cast<unsigned*>(&p2);
    o.w = *reinterpret_cast<unsigned*>(&p3);
    reinterpret_cast<uint4*>(g_xn)[row * (DIM / 8) + lane] = o;
}

// ---------------------------------------------------------------------------
// Kernel 2: fused GEMM + exp + row/col sums, upper-triangular tiles only.
//
// CTA tile 128(M) x 128(N); K=256 in two 128-chunks. 8 warps as 4(M) x 2(N):
// warp tile 32x64. SMEM per chunk: A 128x128 bf16 (32 KB) + B 128x128 (32 KB),
// row-major pitch 256B, 16B-granular XOR swizzle (^ (row&7)<<4).
// blockIdx.x in [0, 2080): triangular decode to (bi <= bj).
// Off-diagonal: row sums -> g_rowsum[bi-block], col sums -> g_rowsum[bj-block]
// (E_ij = E_ji). Diagonal: row sums with diag zeroing only.
// ---------------------------------------------------------------------------
#define SMEM_B_OFF 32768
#define SMEM_TOT   65536
#define NB 64                      // number of 128-row blocks
#define NTILES (NB * (NB + 1) / 2) // 2080

__global__ __launch_bounds__(256) void k_gemm() {
    extern __shared__ char smem[];
    unsigned sb = smem_u32(smem);
    int tid  = threadIdx.x;
    int wid  = tid >> 5, lane = tid & 31;

    // triangular decode: k -> (bi, bj), bi <= bj, row-major upper triangle
    int k = blockIdx.x;
    int bi = (int)floorf((float)NB + 0.5f -
                         sqrtf(((float)NB + 0.5f) * ((float)NB + 0.5f) - 2.0f * (float)k));
    while (NB * (bi + 1) - ((bi + 1) * bi) / 2 <= k) bi++;
    while (NB * bi - (bi * (bi - 1)) / 2 > k) bi--;
    int bj = bi + (k - (NB * bi - (bi * (bi - 1)) / 2));
    bool diag = (bi == bj);

    int warp_m = (wid & 3) * 32;
    int warp_n = (wid >> 2) * 64;

    float acc[2][8][4];
#pragma unroll
    for (int mf = 0; mf < 2; mf++)
#pragma unroll
        for (int nf = 0; nf < 8; nf++)
#pragma unroll
            for (int j = 0; j < 4; j++) acc[mf][nf][j] = 0.0f;

    const uint4* gx = reinterpret_cast<const uint4*>(g_xn);

    for (int kc = 0; kc < 2; kc++) {
        if (kc) __syncthreads();
#pragma unroll
        for (int it = 0; it < 8; it++) {
            int i = tid + it * 256;
            int r = i >> 4, c = i & 15;
            uint4 v = gx[(size_t)(bi * 128 + r) * 32 + kc * 16 + c];
            *reinterpret_cast<uint4*>(smem + r * 256 + ((c << 4) ^ ((r & 7) << 4))) = v;
        }
#pragma unroll
        for (int it = 0; it < 8; it++) {
            int i = tid + it * 256;
            int r = i >> 4, c = i & 15;
            uint4 v = gx[(size_t)(bj * 128 + r) * 32 + kc * 16 + c];
            *reinterpret_cast<uint4*>(smem + SMEM_B_OFF + r * 256 +
                                      ((c << 4) ^ ((r & 7) << 4))) = v;
        }
        __syncthreads();

#pragma unroll
        for (int ks = 0; ks < 8; ks++) {
            unsigned a[2][4];
#pragma unroll
            for (int mf = 0; mf < 2; mf++) {
                int r   = warp_m + mf * 16 + (lane & 15);
                int seg = lane >> 4;
                unsigned addr = sb + r * 256 +
                                (((ks * 2 + seg) << 4) ^ ((r & 7) << 4));
                ldmatrix_x4(a[mf][0], a[mf][1], a[mf][2], a[mf][3], addr);
            }
            unsigned b[8][2];
#pragma unroll
            for (int p = 0; p < 4; p++) {
                int g = lane >> 3, lr = lane & 7;
                int r   = warp_n + p * 16 + (g >> 1) * 8 + lr;
                int seg = g & 1;
                unsigned addr = sb + SMEM_B_OFF + r * 256 +
                                (((ks * 2 + seg) << 4) ^ ((r & 7) << 4));
                unsigned r0, r1, r2, r3;
                ldmatrix_x4(r0, r1, r2, r3, addr);
                b[p * 2 + 0][0] = r0; b[p * 2 + 0][1] = r1;
                b[p * 2 + 1][0] = r2; b[p * 2 + 1][1] = r3;
            }
#pragma unroll
            for (int mf = 0; mf < 2; mf++)
#pragma unroll
                for (int nf = 0; nf < 8; nf++)
                    mma_16816(acc[mf][nf], a[mf], b[nf]);
        }
    }

    // ---- epilogue ----
    __syncthreads();                     // done reading tile smem; reuse for colsum
    float* colsum = reinterpret_cast<float*>(smem);
    if (!diag) {
        if (tid < 128) colsum[tid] = 0.0f;
        __syncthreads();
    }

    float rs[4] = {0.0f, 0.0f, 0.0f, 0.0f};   // rows warp_m + l/4 + {0,8,16,24}
    int lrow = lane >> 2;
#pragma unroll
    for (int nf = 0; nf < 8; nf++) {
        float c0 = 0.0f, c1 = 0.0f;            // column partials (this nf pair)
        int gcol0 = bj * 128 + warp_n + nf * 8 + (lane & 3) * 2;
#pragma unroll
        for (int mf = 0; mf < 2; mf++) {
            int grow0 = bi * 128 + warp_m + mf * 16 + lrow;
            float e0 = ex2f(acc[mf][nf][0] * TAU_INV_LOG2E);
            float e1 = ex2f(acc[mf][nf][1] * TAU_INV_LOG2E);
            float e2 = ex2f(acc[mf][nf][2] * TAU_INV_LOG2E);
            float e3 = ex2f(acc[mf][nf][3] * TAU_INV_LOG2E);
            if (diag) {
                e0 = (gcol0     == grow0    ) ? 0.0f : e0;
                e1 = (gcol0 + 1 == grow0    ) ? 0.0f : e1;
                e2 = (gcol0     == grow0 + 8) ? 0.0f : e2;
                e3 = (gcol0 + 1 == grow0 + 8) ? 0.0f : e3;
            }
            rs[mf * 2 + 0] += e0 + e1;
            rs[mf * 2 + 1] += e2 + e3;
            c0 += e0 + e2;
            c1 += e1 + e3;
        }
        if (!diag) {
            // reduce over the 8 row-lanes sharing this (lane&3)
#pragma unroll
            for (int o = 4; o <= 16; o <<= 1) {
                c0 += __shfl_xor_sync(0xFFFFFFFFu, c0, o);
                c1 += __shfl_xor_sync(0xFFFFFFFFu, c1, o);
            }
            if (lane < 4) {
                int cc = warp_n + nf * 8 + lane * 2;
                atomicAdd(&colsum[cc],     c0);
                atomicAdd(&colsum[cc + 1], c1);
            }
        }
    }

    // row-sum reduce (over lane&3) + global add
#pragma unroll
    for (int o = 1; o <= 2; o <<= 1)
#pragma unroll
        for (int j = 0; j < 4; j++)
            rs[j] += __shfl_xor_sync(0xFFFFFFFFu, rs[j], o);
    if ((lane & 3) == 0) {
        int r0 = bi * 128 + warp_m + lrow;
        atomicAdd(&g_rowsum[r0],      rs[0]);
        atomicAdd(&g_rowsum[r0 + 8],  rs[1]);
        atomicAdd(&g_rowsum[r0 + 16], rs[2]);
        atomicAdd(&g_rowsum[r0 + 24], rs[3]);
    }

    if (!diag) {
        __syncthreads();
        if (tid < 128) atomicAdd(&g_rowsum[bj * 128 + tid], colsum[tid]);
    }
}

// ---------------------------------------------------------------------------
// Kernel 3: loss = mean_i log(rowsum_i / (N-1) + eps)
// ---------------------------------------------------------------------------
__global__ __launch_bounds__(256) void k_reduce(float* __restrict__ out) {
    __shared__ float sh[8];
    int tid = threadIdx.x;
    float s = 0.0f;
    for (int i = tid; i < NROWS; i += 256)
        s += logf(g_rowsum[i] * (1.0f / (float)(NROWS - 1)) + EPS);
#pragma unroll
    for (int o = 16; o; o >>= 1) s += __shfl_xor_sync(0xFFFFFFFFu, s, o);
    if ((tid & 31) == 0) sh[tid >> 5] = s;
    __syncthreads();
    if (tid == 0) {
        float t = 0.0f;
#pragma unroll
        for (int i = 0; i < 8; i++) t += sh[i];
        out[0] = t * (1.0f / (float)NROWS);
    }
}

// ---------------------------------------------------------------------------
extern "C" void kernel_launch(void* const* d_in, const int* in_sizes, int n_in,
                              void* d_out, int out_size) {
    (void)in_sizes; (void)n_in; (void)out_size;
    const float* x = (const float*)d_in[0];

    cudaFuncSetAttribute(k_gemm, cudaFuncAttributeMaxDynamicSharedMemorySize, SMEM_TOT);

    k_normalize<<<NROWS / 8, 256>>>(x);
    k_gemm<<<NTILES, 256, SMEM_TOT>>>();
    k_reduce<<<1, 256>>>((float*)d_out);
}

// round 8
// speedup vs baseline: 1.8223x; 1.6970x over previous
#include <cuda_runtime.h>
#include <cuda_bf16.h>
#include <cstdint>

// ============================================================================
// NegativeContrastiveLoss: x[8192,256] fp32 ->
//   xn = x / max(||x||_2, 1e-12)  (rows)
//   S  = xn @ xn^T / 0.1 ; E = exp(S) with diag zeroed
//   loss = mean_i log( sum_j E_ij / (N-1) + 1e-8 )
//
// R7: cp.async double-buffered mainloop (4 K-chunks of 64, 2 stages) +
//     __launch_bounds__(256,2) to force occupancy 2 (regs <= 128).
//     Keeps R6 symmetry: only 2080 upper-triangular 128x128 tiles; off-diag
//     tiles contribute row sums (block bi) AND column sums (block bj).
//
// mma.sync m16n8k16 bf16 path (compute_103 family target rejects tcgen05).
// ============================================================================

#define NROWS 8192
#define DIM   256
#define TAU_INV_LOG2E 14.4269504088896340736f   // (1/0.1) * log2(e)
#define EPS   1e-8f

__device__ __align__(256) __nv_bfloat16 g_xn[NROWS * DIM];   // 4 MB, L2-resident
__device__ float g_rowsum[NROWS];

static __device__ __forceinline__ unsigned smem_u32(const void* p) {
    unsigned a;
    asm("{ .reg .u64 t; cvta.to.shared.u64 t, %1; cvt.u32.u64 %0, t; }" : "=r"(a) : "l"(p));
    return a;
}
static __device__ __forceinline__ void cp_async16(unsigned saddr, const void* gptr) {
    asm volatile("cp.async.cg.shared.global [%0], [%1], 16;"
                 :: "r"(saddr), "l"(gptr) : "memory");
}
static __device__ __forceinline__ void ldmatrix_x4(unsigned& r0, unsigned& r1,
                                                   unsigned& r2, unsigned& r3,
                                                   unsigned addr) {
    asm volatile("ldmatrix.sync.aligned.m8n8.x4.shared.b16 {%0,%1,%2,%3}, [%4];"
                 : "=r"(r0), "=r"(r1), "=r"(r2), "=r"(r3) : "r"(addr));
}
static __device__ __forceinline__ void mma_16816(float* c, const unsigned* a,
                                                 const unsigned* b) {
    asm volatile(
        "mma.sync.aligned.m16n8k16.row.col.f32.bf16.bf16.f32 "
        "{%0,%1,%2,%3}, {%4,%5,%6,%7}, {%8,%9}, {%0,%1,%2,%3};"
        : "+f"(c[0]), "+f"(c[1]), "+f"(c[2]), "+f"(c[3])
        : "r"(a[0]), "r"(a[1]), "r"(a[2]), "r"(a[3]), "r"(b[0]), "r"(b[1]));
}
static __device__ __forceinline__ float ex2f(float v) {
    float e;
    asm("ex2.approx.f32 %0, %1;" : "=f"(e) : "f"(v));
    return e;
}

// ---------------------------------------------------------------------------
// Kernel 1: row L2-normalize -> bf16, zero rowsum. 1 warp per row.
// ---------------------------------------------------------------------------
__global__ __launch_bounds__(256) void k_normalize(const float* __restrict__ x) {
    int tid = threadIdx.x;
    int gt = blockIdx.x * 256 + tid;
    if (gt < NROWS) g_rowsum[gt] = 0.0f;

    int row  = blockIdx.x * 8 + (tid >> 5);
    int lane = tid & 31;
    const float4* xr = reinterpret_cast<const float4*>(x) + (size_t)row * (DIM / 4);
    float4 a = xr[lane * 2 + 0];
    float4 b = xr[lane * 2 + 1];
    float s = a.x * a.x + a.y * a.y + a.z * a.z + a.w * a.w +
              b.x * b.x + b.y * b.y + b.z * b.z + b.w * b.w;
#pragma unroll
    for (int o = 16; o; o >>= 1) s += __shfl_xor_sync(0xFFFFFFFFu, s, o);
    float scale = 1.0f / fmaxf(sqrtf(s), 1e-12f);

    __nv_bfloat162 p0 = __floats2bfloat162_rn(a.x * scale, a.y * scale);
    __nv_bfloat162 p1 = __floats2bfloat162_rn(a.z * scale, a.w * scale);
    __nv_bfloat162 p2 = __floats2bfloat162_rn(b.x * scale, b.y * scale);
    __nv_bfloat162 p3 = __floats2bfloat162_rn(b.z * scale, b.w * scale);
    uint4 o;
    o.x = *reinterpret_cast<unsigned*>(&p0);
    o.y = *reinterpret_cast<unsigned*>(&p1);
    o.z = *reinterpret_cast<unsigned*>(&p2);
    o.w = *reinterpret_cast<unsigned*>(&p3);
    reinterpret_cast<uint4*>(g_xn)[row * (DIM / 8) + lane] = o;
}

// ---------------------------------------------------------------------------
// Kernel 2: fused GEMM + exp + row/col sums, upper-triangular tiles only.
//
// CTA tile 128(M) x 128(N). K=256 in 4 chunks of 64, 2-stage cp.async
// double buffer: A/B chunk buffers 128x64 bf16 = 16 KB each; 4 buffers = 64 KB.
// Buffer layout: row pitch 128B, 16B-granule XOR swizzle (c ^ (r&7)).
// 8 warps as 4(M) x 2(N), warp tile 32x64.
// blockIdx.x in [0, 2080): triangular decode to (bi <= bj).
// ---------------------------------------------------------------------------
#define STAGE_BYTES 32768           // A(16K) + B(16K) per stage
#define SMEM_TOT    65536
#define NB 64
#define NTILES (NB * (NB + 1) / 2)  // 2080
#define NKC 4                        // K chunks of 64

__global__ __launch_bounds__(256, 2) void k_gemm() {
    extern __shared__ char smem[];
    unsigned sb = smem_u32(smem);
    int tid  = threadIdx.x;
    int wid  = tid >> 5, lane = tid & 31;

    // triangular decode: k -> (bi, bj), bi <= bj
    int k = blockIdx.x;
    int bi = (int)floorf((float)NB + 0.5f -
                         sqrtf(((float)NB + 0.5f) * ((float)NB + 0.5f) - 2.0f * (float)k));
    while (NB * (bi + 1) - ((bi + 1) * bi) / 2 <= k) bi++;
    while (NB * bi - (bi * (bi - 1)) / 2 > k) bi--;
    int bj = bi + (k - (NB * bi - (bi * (bi - 1)) / 2));
    bool diag = (bi == bj);

    int warp_m = (wid & 3) * 32;
    int warp_n = (wid >> 2) * 64;

    // per-thread load coords (fixed across stages): 4 iters x 256 thr = 1024 16B
    int lr = tid >> 3;                 // row base (0..31), +32 per iter
    int lc = tid & 7;                  // 16B chunk within 64-col row
    unsigned ssw = (unsigned)((lc ^ (lr & 7)) << 4);
    const char* gA = reinterpret_cast<const char*>(g_xn) + (size_t)(bi * 128 + lr) * 512 + lc * 16;
    const char* gB = reinterpret_cast<const char*>(g_xn) + (size_t)(bj * 128 + lr) * 512 + lc * 16;

#define ISSUE_STAGE(kc, buf)                                                     \
    do {                                                                         \
        unsigned ab = sb + (buf) * STAGE_BYTES;                                  \
        unsigned bb = ab + 16384;                                                \
        _Pragma("unroll")                                                        \
        for (int it = 0; it < 4; it++)                                           \
            cp_async16(ab + (unsigned)(lr + it * 32) * 128 + ssw,                \
                       gA + (size_t)it * 32 * 512 + (kc) * 128);                 \
        _Pragma("unroll")                                                        \
        for (int it = 0; it < 4; it++)                                           \
            cp_async16(bb + (unsigned)(lr + it * 32) * 128 + ssw,                \
                       gB + (size_t)it * 32 * 512 + (kc) * 128);                 \
        asm volatile("cp.async.commit_group;" ::: "memory");                     \
    } while (0)

    float acc[2][8][4];
#pragma unroll
    for (int mf = 0; mf < 2; mf++)
#pragma unroll
        for (int nf = 0; nf < 8; nf++)
#pragma unroll
            for (int j = 0; j < 4; j++) acc[mf][nf][j] = 0.0f;

    // prologue: stages 0 and 1 in flight
    ISSUE_STAGE(0, 0);
    ISSUE_STAGE(1, 1);

#pragma unroll
    for (int kc = 0; kc < NKC; kc++) {
        if (kc == NKC - 1) asm volatile("cp.async.wait_group 0;" ::: "memory");
        else               asm volatile("cp.async.wait_group 1;" ::: "memory");
        __syncthreads();

        unsigned ab = sb + (kc & 1) * STAGE_BYTES;
        unsigned bb = ab + 16384;

#pragma unroll
        for (int ks = 0; ks < 4; ks++) {
            unsigned a[2][4];
#pragma unroll
            for (int mf = 0; mf < 2; mf++) {
                int r = warp_m + mf * 16 + (lane & 15);
                int ch = ks * 2 + (lane >> 4);
                ldmatrix_x4(a[mf][0], a[mf][1], a[mf][2], a[mf][3],
                            ab + r * 128 + ((ch ^ (r & 7)) << 4));
            }
            unsigned b[8][2];
#pragma unroll
            for (int p = 0; p < 4; p++) {
                int g = lane >> 3;
                int r = warp_n + p * 16 + (g >> 1) * 8 + (lane & 7);
                int ch = ks * 2 + (g & 1);
                unsigned r0, r1, r2, r3;
                ldmatrix_x4(r0, r1, r2, r3, bb + r * 128 + ((ch ^ (r & 7)) << 4));
                b[p * 2 + 0][0] = r0; b[p * 2 + 0][1] = r1;
                b[p * 2 + 1][0] = r2; b[p * 2 + 1][1] = r3;
            }
#pragma unroll
            for (int mf = 0; mf < 2; mf++)
#pragma unroll
                for (int nf = 0; nf < 8; nf++)
                    mma_16816(acc[mf][nf], a[mf], b[nf]);
        }

        if (kc + 2 < NKC) {
            __syncthreads();               // all warps done reading buf kc&1
            ISSUE_STAGE(kc + 2, kc & 1);
        }
    }

    // ---- epilogue: exp, diag zero, row sums + (off-diag) column sums ----
    __syncthreads();
    float* colsum = reinterpret_cast<float*>(smem);
    if (!diag) {
        if (tid < 128) colsum[tid] = 0.0f;
        __syncthreads();
    }

    float rs[4] = {0.0f, 0.0f, 0.0f, 0.0f};
    int lrow = lane >> 2;
#pragma unroll
    for (int nf = 0; nf < 8; nf++) {
        float c0 = 0.0f, c1 = 0.0f;
        int gcol0 = bj * 128 + warp_n + nf * 8 + (lane & 3) * 2;
#pragma unroll
        for (int mf = 0; mf < 2; mf++) {
            int grow0 = bi * 128 + warp_m + mf * 16 + lrow;
            float e0 = ex2f(acc[mf][nf][0] * TAU_INV_LOG2E);
            float e1 = ex2f(acc[mf][nf][1] * TAU_INV_LOG2E);
            float e2 = ex2f(acc[mf][nf][2] * TAU_INV_LOG2E);
            float e3 = ex2f(acc[mf][nf][3] * TAU_INV_LOG2E);
            if (diag) {
                e0 = (gcol0     == grow0    ) ? 0.0f : e0;
                e1 = (gcol0 + 1 == grow0    ) ? 0.0f : e1;
                e2 = (gcol0     == grow0 + 8) ? 0.0f : e2;
                e3 = (gcol0 + 1 == grow0 + 8) ? 0.0f : e3;
            }
            rs[mf * 2 + 0] += e0 + e1;
            rs[mf * 2 + 1] += e2 + e3;
            c0 += e0 + e2;
            c1 += e1 + e3;
        }
        if (!diag) {
#pragma unroll
            for (int o = 4; o <= 16; o <<= 1) {
                c0 += __shfl_xor_sync(0xFFFFFFFFu, c0, o);
                c1 += __shfl_xor_sync(0xFFFFFFFFu, c1, o);
            }
            if (lane < 4) {
                int cc = warp_n + nf * 8 + lane * 2;
                atomicAdd(&colsum[cc],     c0);
                atomicAdd(&colsum[cc + 1], c1);
            }
        }
    }

#pragma unroll
    for (int o = 1; o <= 2; o <<= 1)
#pragma unroll
        for (int j = 0; j < 4; j++)
            rs[j] += __shfl_xor_sync(0xFFFFFFFFu, rs[j], o);
    if ((lane & 3) == 0) {
        int r0 = bi * 128 + warp_m + lrow;
        atomicAdd(&g_rowsum[r0],      rs[0]);
        atomicAdd(&g_rowsum[r0 + 8],  rs[1]);
        atomicAdd(&g_rowsum[r0 + 16], rs[2]);
        atomicAdd(&g_rowsum[r0 + 24], rs[3]);
    }

    if (!diag) {
        __syncthreads();
        if (tid < 128) atomicAdd(&g_rowsum[bj * 128 + tid], colsum[tid]);
    }
#undef ISSUE_STAGE
}

// ---------------------------------------------------------------------------
// Kernel 3: loss = mean_i log(rowsum_i / (N-1) + eps)
// ---------------------------------------------------------------------------
__global__ __launch_bounds__(256) void k_reduce(float* __restrict__ out) {
    __shared__ float sh[8];
    int tid = threadIdx.x;
    float s = 0.0f;
    for (int i = tid; i < NROWS; i += 256)
        s += logf(g_rowsum[i] * (1.0f / (float)(NROWS - 1)) + EPS);
#pragma unroll
    for (int o = 16; o; o >>= 1) s += __shfl_xor_sync(0xFFFFFFFFu, s, o);
    if ((tid & 31) == 0) sh[tid >> 5] = s;
    __syncthreads();
    if (tid == 0) {
        float t = 0.0f;
#pragma unroll
        for (int i = 0; i < 8; i++) t += sh[i];
        out[0] = t * (1.0f / (float)NROWS);
    }
}

// ---------------------------------------------------------------------------
extern "C" void kernel_launch(void* const* d_in, const int* in_sizes, int n_in,
                              void* d_out, int out_size) {
    (void)in_sizes; (void)n_in; (void)out_size;
    const float* x = (const float*)d_in[0];

    cudaFuncSetAttribute(k_gemm, cudaFuncAttributeMaxDynamicSharedMemorySize, SMEM_TOT);

    k_normalize<<<NROWS / 8, 256>>>(x);
    k_gemm<<<NTILES, 256, SMEM_TOT>>>();
    k_reduce<<<1, 256>>>((float*)d_out);
}

// round 10
// speedup vs baseline: 1.9249x; 1.0563x over previous
#include <cuda_runtime.h>
#include <cuda_bf16.h>
#include <cstdint>

// ============================================================================
// NegativeContrastiveLoss: x[8192,256] fp32 ->
//   xn = x / max(||x||_2, 1e-12)  (rows)
//   S  = xn @ xn^T / 0.1 ; E = exp(S) with diag zeroed
//   loss = mean_i log( sum_j E_ij / (N-1) + 1e-8 )
//
// R8: 3-stage cp.async pipeline (96 KB smem, one __syncthreads per K-chunk,
//     issue-before-compute) + parallel k_reduce (atomicAdd into out).
//     Keeps R6 symmetry (2080 upper-triangular 128x128 tiles, row+col sums)
//     and R7 occupancy-2 mma.sync mainloop.
// ============================================================================

#define NROWS 8192
#define DIM   256
#define TAU_INV_LOG2E 14.4269504088896340736f   // (1/0.1) * log2(e)
#define EPS   1e-8f

__device__ __align__(256) __nv_bfloat16 g_xn[NROWS * DIM];   // 4 MB, L2-resident
__device__ float g_rowsum[NROWS];

static __device__ __forceinline__ unsigned smem_u32(const void* p) {
    unsigned a;
    asm("{ .reg .u64 t; cvta.to.shared.u64 t, %1; cvt.u32.u64 %0, t; }" : "=r"(a) : "l"(p));
    return a;
}
static __device__ __forceinline__ void cp_async16(unsigned saddr, const void* gptr) {
    asm volatile("cp.async.cg.shared.global [%0], [%1], 16;"
                 :: "r"(saddr), "l"(gptr) : "memory");
}
static __device__ __forceinline__ void ldmatrix_x4(unsigned& r0, unsigned& r1,
                                                   unsigned& r2, unsigned& r3,
                                                   unsigned addr) {
    asm volatile("ldmatrix.sync.aligned.m8n8.x4.shared.b16 {%0,%1,%2,%3}, [%4];"
                 : "=r"(r0), "=r"(r1), "=r"(r2), "=r"(r3) : "r"(addr));
}
static __device__ __forceinline__ void mma_16816(float* c, const unsigned* a,
                                                 const unsigned* b) {
    asm volatile(
        "mma.sync.aligned.m16n8k16.row.col.f32.bf16.bf16.f32 "
        "{%0,%1,%2,%3}, {%4,%5,%6,%7}, {%8,%9}, {%0,%1,%2,%3};"
        : "+f"(c[0]), "+f"(c[1]), "+f"(c[2]), "+f"(c[3])
        : "r"(a[0]), "r"(a[1]), "r"(a[2]), "r"(a[3]), "r"(b[0]), "r"(b[1]));
}
static __device__ __forceinline__ float ex2f(float v) {
    float e;
    asm("ex2.approx.f32 %0, %1;" : "=f"(e) : "f"(v));
    return e;
}

// ---------------------------------------------------------------------------
// Kernel 1: row L2-normalize -> bf16, zero rowsum and out[0]. 1 warp per row.
// ---------------------------------------------------------------------------
__global__ __launch_bounds__(256) void k_normalize(const float* __restrict__ x,
                                                   float* __restrict__ out) {
    int tid = threadIdx.x;
    int gt = blockIdx.x * 256 + tid;
    if (gt < NROWS) g_rowsum[gt] = 0.0f;
    if (gt == 0) out[0] = 0.0f;

    int row  = blockIdx.x * 8 + (tid >> 5);
    int lane = tid & 31;
    const float4* xr = reinterpret_cast<const float4*>(x) + (size_t)row * (DIM / 4);
    float4 a = xr[lane * 2 + 0];
    float4 b = xr[lane * 2 + 1];
    float s = a.x * a.x + a.y * a.y + a.z * a.z + a.w * a.w +
              b.x * b.x + b.y * b.y + b.z * b.z + b.w * b.w;
#pragma unroll
    for (int o = 16; o; o >>= 1) s += __shfl_xor_sync(0xFFFFFFFFu, s, o);
    float scale = 1.0f / fmaxf(sqrtf(s), 1e-12f);

    __nv_bfloat162 p0 = __floats2bfloat162_rn(a.x * scale, a.y * scale);
    __nv_bfloat162 p1 = __floats2bfloat162_rn(a.z * scale, a.w * scale);
    __nv_bfloat162 p2 = __floats2bfloat162_rn(b.x * scale, b.y * scale);
    __nv_bfloat162 p3 = __floats2bfloat162_rn(b.z * scale, b.w * scale);
    uint4 o;
    o.x = *reinterpret_cast<unsigned*>(&p0);
    o.y = *reinterpret_cast<unsigned*>(&p1);
    o.z = *reinterpret_cast<unsigned*>(&p2);
    o.w = *reinterpret_cast<unsigned*>(&p3);
    reinterpret_cast<uint4*>(g_xn)[row * (DIM / 8) + lane] = o;
}

// ---------------------------------------------------------------------------
// Kernel 2: fused GEMM + exp + row/col sums, upper-triangular tiles only.
//
// CTA tile 128(M) x 128(N). K=256 in 4 chunks of 64, 3-stage cp.async
// pipeline: A/B chunk buffers 128x64 bf16 = 16 KB each; stage = 32 KB,
// 3 stages = 96 KB. Row pitch 128B, 16B-granule XOR swizzle (c ^ (r&7)).
// One __syncthreads per chunk; chunk kc+2 issued before computing chunk kc
// (its buffer was last read at iter kc-1, protected by this iter's barrier).
// 8 warps as 4(M) x 2(N), warp tile 32x64.
// blockIdx.x in [0, 2080): triangular decode to (bi <= bj).
// ---------------------------------------------------------------------------
#define STAGE_BYTES 32768
#define SMEM_TOT    98304           // 3 stages
#define NB 64
#define NTILES (NB * (NB + 1) / 2)  // 2080
#define NKC 4                        // K chunks of 64

__global__ __launch_bounds__(256, 2) void k_gemm() {
    extern __shared__ char smem[];
    unsigned sb = smem_u32(smem);
    int tid  = threadIdx.x;
    int wid  = tid >> 5, lane = tid & 31;

    // triangular decode: k -> (bi, bj), bi <= bj
    int k = blockIdx.x;
    int bi = (int)floorf((float)NB + 0.5f -
                         sqrtf(((float)NB + 0.5f) * ((float)NB + 0.5f) - 2.0f * (float)k));
    while (NB * (bi + 1) - ((bi + 1) * bi) / 2 <= k) bi++;
    while (NB * bi - (bi * (bi - 1)) / 2 > k) bi--;
    int bj = bi + (k - (NB * bi - (bi * (bi - 1)) / 2));
    bool diag = (bi == bj);

    int warp_m = (wid & 3) * 32;
    int warp_n = (wid >> 2) * 64;

    // per-thread load coords: 4 iters x 256 thr = 1024 x 16B per 128x64 buffer
    int lr = tid >> 3;                 // row base (0..31), +32 per iter
    int lc = tid & 7;                  // 16B chunk within 64-col row
    unsigned ssw = (unsigned)((lc ^ (lr & 7)) << 4);
    const char* gA = reinterpret_cast<const char*>(g_xn) + (size_t)(bi * 128 + lr) * 512 + lc * 16;
    const char* gB = reinterpret_cast<const char*>(g_xn) + (size_t)(bj * 128 + lr) * 512 + lc * 16;

#define ISSUE_STAGE(kc, buf)                                                     \
    do {                                                                         \
        unsigned ab = sb + (buf) * STAGE_BYTES;                                  \
        unsigned bb = ab + 16384;                                                \
        _Pragma("unroll")                                                        \
        for (int it = 0; it < 4; it++)                                           \
            cp_async16(ab + (unsigned)(lr + it * 32) * 128 + ssw,                \
                       gA + (size_t)it * 32 * 512 + (kc) * 128);                 \
        _Pragma("unroll")                                                        \
        for (int it = 0; it < 4; it++)                                           \
            cp_async16(bb + (unsigned)(lr + it * 32) * 128 + ssw,                \
                       gB + (size_t)it * 32 * 512 + (kc) * 128);                 \
        asm volatile("cp.async.commit_group;" ::: "memory");                     \
    } while (0)

    float acc[2][8][4];
#pragma unroll
    for (int mf = 0; mf < 2; mf++)
#pragma unroll
        for (int nf = 0; nf < 8; nf++)
#pragma unroll
            for (int j = 0; j < 4; j++) acc[mf][nf][j] = 0.0f;

    // prologue: chunks 0,1 in flight (buffers 0,1)
    ISSUE_STAGE(0, 0);
    ISSUE_STAGE(1, 1);

#pragma unroll
    for (int kc = 0; kc < NKC; kc++) {
        if (kc < NKC - 1) asm volatile("cp.async.wait_group 1;" ::: "memory");
        else              asm volatile("cp.async.wait_group 0;" ::: "memory");
        __syncthreads();   // chunk kc visible to all; all warps past iter kc-1

        // issue chunk kc+2 into buffer (kc+2)%3 (last read at iter kc-1)
        if (kc + 2 < NKC) ISSUE_STAGE(kc + 2, (kc + 2) % 3);

        unsigned ab = sb + (kc % 3) * STAGE_BYTES;
        unsigned bb = ab + 16384;

#pragma unroll
        for (int ks = 0; ks < 4; ks++) {
            unsigned a[2][4];
#pragma unroll
            for (int mf = 0; mf < 2; mf++) {
                int r = warp_m + mf * 16 + (lane & 15);
                int ch = ks * 2 + (lane >> 4);
                ldmatrix_x4(a[mf][0], a[mf][1], a[mf][2], a[mf][3],
                            ab + r * 128 + ((ch ^ (r & 7)) << 4));
            }
            unsigned b[8][2];
#pragma unroll
            for (int p = 0; p < 4; p++) {
                int g = lane >> 3;
                int r = warp_n + p * 16 + (g >> 1) * 8 + (lane & 7);
                int ch = ks * 2 + (g & 1);
                unsigned r0, r1, r2, r3;
                ldmatrix_x4(r0, r1, r2, r3, bb + r * 128 + ((ch ^ (r & 7)) << 4));
                b[p * 2 + 0][0] = r0; b[p * 2 + 0][1] = r1;
                b[p * 2 + 1][0] = r2; b[p * 2 + 1][1] = r3;
            }
#pragma unroll
            for (int mf = 0; mf < 2; mf++)
#pragma unroll
                for (int nf = 0; nf < 8; nf++)
                    mma_16816(acc[mf][nf], a[mf], b[nf]);
        }
    }

    // ---- epilogue: exp, diag zero, row sums + (off-diag) column sums ----
    __syncthreads();
    float* colsum = reinterpret_cast<float*>(smem);
    if (!diag) {
        if (tid < 128) colsum[tid] = 0.0f;
        __syncthreads();
    }

    float rs[4] = {0.0f, 0.0f, 0.0f, 0.0f};
    int lrow = lane >> 2;
#pragma unroll
    for (int nf = 0; nf < 8; nf++) {
        float c0 = 0.0f, c1 = 0.0f;
        int gcol0 = bj * 128 + warp_n + nf * 8 + (lane & 3) * 2;
#pragma unroll
        for (int mf = 0; mf < 2; mf++) {
            int grow0 = bi * 128 + warp_m + mf * 16 + lrow;
            float e0 = ex2f(acc[mf][nf][0] * TAU_INV_LOG2E);
            float e1 = ex2f(acc[mf][nf][1] * TAU_INV_LOG2E);
            float e2 = ex2f(acc[mf][nf][2] * TAU_INV_LOG2E);
            float e3 = ex2f(acc[mf][nf][3] * TAU_INV_LOG2E);
            if (diag) {
                e0 = (gcol0     == grow0    ) ? 0.0f : e0;
                e1 = (gcol0 + 1 == grow0    ) ? 0.0f : e1;
                e2 = (gcol0     == grow0 + 8) ? 0.0f : e2;
                e3 = (gcol0 + 1 == grow0 + 8) ? 0.0f : e3;
            }
            rs[mf * 2 + 0] += e0 + e1;
            rs[mf * 2 + 1] += e2 + e3;
            c0 += e0 + e2;
            c1 += e1 + e3;
        }
        if (!diag) {
#pragma unroll
            for (int o = 4; o <= 16; o <<= 1) {
                c0 += __shfl_xor_sync(0xFFFFFFFFu, c0, o);
                c1 += __shfl_xor_sync(0xFFFFFFFFu, c1, o);
            }
            if (lane < 4) {
                int cc = warp_n + nf * 8 + lane * 2;
                atomicAdd(&colsum[cc],     c0);
                atomicAdd(&colsum[cc + 1], c1);
            }
        }
    }

#pragma unroll
    for (int o = 1; o <= 2; o <<= 1)
#pragma unroll
        for (int j = 0; j < 4; j++)
            rs[j] += __shfl_xor_sync(0xFFFFFFFFu, rs[j], o);
    if ((lane & 3) == 0) {
        int r0 = bi * 128 + warp_m + lrow;
        atomicAdd(&g_rowsum[r0],      rs[0]);
        atomicAdd(&g_rowsum[r0 + 8],  rs[1]);
        atomicAdd(&g_rowsum[r0 + 16], rs[2]);
        atomicAdd(&g_rowsum[r0 + 24], rs[3]);
    }

    if (!diag) {
        __syncthreads();
        if (tid < 128) atomicAdd(&g_rowsum[bj * 128 + tid], colsum[tid]);
    }
#undef ISSUE_STAGE
}

// ---------------------------------------------------------------------------
// Kernel 3 (parallel): out[0] += block partial of mean log(rowsum/(N-1)+eps)
// 32 blocks x 256 threads, one row per thread.
// ---------------------------------------------------------------------------
__global__ __launch_bounds__(256) void k_reduce(float* __restrict__ out) {
    __shared__ float sh[8];
    int tid = threadIdx.x;
    int i = blockIdx.x * 256 + tid;
    float s = logf(g_rowsum[i] * (1.0f / (float)(NROWS - 1)) + EPS);
#pragma unroll
    for (int o = 16; o; o >>= 1) s += __shfl_xor_sync(0xFFFFFFFFu, s, o);
    if ((tid & 31) == 0) sh[tid >> 5] = s;
    __syncthreads();
    if (tid == 0) {
        float t = 0.0f;
#pragma unroll
        for (int j = 0; j < 8; j++) t += sh[j];
        atomicAdd(out, t * (1.0f / (float)NROWS));
    }
}

// ---------------------------------------------------------------------------
extern "C" void kernel_launch(void* const* d_in, const int* in_sizes, int n_in,
                              void* d_out, int out_size) {
    (void)in_sizes; (void)n_in; (void)out_size;
    const float* x = (const float*)d_in[0];

    cudaFuncSetAttribute(k_gemm, cudaFuncAttributeMaxDynamicSharedMemorySize, SMEM_TOT);

    k_normalize<<<NROWS / 8, 256>>>(x, (float*)d_out);
    k_gemm<<<NTILES, 256, SMEM_TOT>>>();
    k_reduce<<<NROWS / 256, 256>>>((float*)d_out);
}